// round 2
// baseline (speedup 1.0000x reference)
#include <cuda_runtime.h>
#include <math.h>
#include <stdint.h>

#define S_LEN 2048
#define BATCH 4
#define HID 1024
#define NHEADS 16
#define HDIM 64
#define M_ROWS (S_LEN * BATCH)   // 8192
#define QKV_N (3 * HID)          // 3072
#define MASK_VAL (-10000.0f)

// Scratch (allocation-free: device globals)
__device__ float g_mixed[(size_t)M_ROWS * QKV_N];   // 96 MB: QKV output
__device__ float g_ctx[(size_t)M_ROWS * HID];       // 32 MB: attention context
__device__ int   g_mask_is_i32;                     // mask dtype flag

// ---------------------------------------------------------------------------
// Mask dtype detection: jax bool may arrive as int32 (widened) or uint8.
// If the first 1024 int32 words are all 0/1, it's int32; random packed 0/1
// bytes would make words like 0x00010001 (>1) almost immediately.
// ---------------------------------------------------------------------------
__global__ void detect_mask_dtype(const int* __restrict__ mask_as_i32) {
    int ok = 1;
    for (int i = 0; i < 1024; i++) {
        unsigned v = (unsigned)mask_as_i32[i];
        if (v > 1u) { ok = 0; break; }
    }
    g_mask_is_i32 = ok;
}

// ---------------------------------------------------------------------------
// Tiled SGEMM:  C[m][n] = sum_k A[m][k] * B[n][k] + bias[n]
// BM=BN=64, BK=16, 256 threads, 4x4 micro-tile per thread.
// ---------------------------------------------------------------------------
template <int N_DIM, int K_DIM>
__global__ void __launch_bounds__(256)
gemm_nt_bias(const float* __restrict__ A,
             const float* __restrict__ Bm,
             const float* __restrict__ bias,
             float* __restrict__ C) {
    __shared__ float As[16][64];
    __shared__ float Bs[16][64];

    const int m0 = blockIdx.y * 64;
    const int n0 = blockIdx.x * 64;
    const int tid = threadIdx.x;
    const int ty = tid >> 4;        // 0..15
    const int tx = tid & 15;        // 0..15
    const int lrow = tid >> 2;      // 0..63 loader row
    const int lk4  = (tid & 3) * 4; // 0,4,8,12

    float acc[4][4] = {};

    for (int k0 = 0; k0 < K_DIM; k0 += 16) {
        float4 av = *(const float4*)(A  + (size_t)(m0 + lrow) * K_DIM + k0 + lk4);
        float4 bv = *(const float4*)(Bm + (size_t)(n0 + lrow) * K_DIM + k0 + lk4);
        As[lk4 + 0][lrow] = av.x; As[lk4 + 1][lrow] = av.y;
        As[lk4 + 2][lrow] = av.z; As[lk4 + 3][lrow] = av.w;
        Bs[lk4 + 0][lrow] = bv.x; Bs[lk4 + 1][lrow] = bv.y;
        Bs[lk4 + 2][lrow] = bv.z; Bs[lk4 + 3][lrow] = bv.w;
        __syncthreads();

#pragma unroll
        for (int kk = 0; kk < 16; kk++) {
            float a[4], b[4];
#pragma unroll
            for (int i = 0; i < 4; i++) a[i] = As[kk][ty * 4 + i];
#pragma unroll
            for (int j = 0; j < 4; j++) b[j] = Bs[kk][tx * 4 + j];
#pragma unroll
            for (int i = 0; i < 4; i++)
#pragma unroll
                for (int j = 0; j < 4; j++)
                    acc[i][j] = fmaf(a[i], b[j], acc[i][j]);
        }
        __syncthreads();
    }

#pragma unroll
    for (int i = 0; i < 4; i++) {
        const int m = m0 + ty * 4 + i;
#pragma unroll
        for (int j = 0; j < 4; j++) {
            const int n = n0 + tx * 4 + j;
            C[(size_t)m * N_DIM + n] = acc[i][j] + bias[n];
        }
    }
}

// ---------------------------------------------------------------------------
// Flash attention (fp32). Grid: x = q-tile (32), y = b*NH + h (64).
// 256 threads; thread handles row r=tid/4, ctx cols [quad*16, quad*16+16).
// mixed layout: g_mixed[(s*B+b)*3072 + h*192 + {0:q, 64:k, 128:v} + d]
// ---------------------------------------------------------------------------
__global__ void __launch_bounds__(256)
attention_kernel(const void* __restrict__ mask_raw,
                 float* __restrict__ ctx_out) {
    extern __shared__ float smem[];
    float* Qs = smem;                 // [64][64]
    float* Ks = Qs + 64 * 64;         // [64][65] (padded)
    float* Vs = Ks + 64 * 65;         // [64][64]
    float* Ps = Vs + 64 * 64;         // [64][65] probabilities (padded)

    const int qt = blockIdx.x;            // 0..31
    const int bh = blockIdx.y;            // 0..63
    const int b  = bh / NHEADS;
    const int h  = bh % NHEADS;

    const int tid  = threadIdx.x;
    const int r    = tid >> 2;            // 0..63 (row of tile)
    const int quad = tid & 3;
    const int c0   = quad * 16;

    const int mask_i32 = g_mask_is_i32;
    const unsigned char* mask_u8 = (const unsigned char*)mask_raw;
    const int* mask_32 = (const int*)mask_raw;

    // Load Q tile
    {
        const int s = qt * 64 + r;
        const float* src = g_mixed + (size_t)(s * BATCH + b) * QKV_N + h * 192;
#pragma unroll
        for (int i = 0; i < 16; i += 4) {
            float4 v = *(const float4*)(src + c0 + i);
            Qs[r * 64 + c0 + i + 0] = v.x;
            Qs[r * 64 + c0 + i + 1] = v.y;
            Qs[r * 64 + c0 + i + 2] = v.z;
            Qs[r * 64 + c0 + i + 3] = v.w;
        }
    }

    float m_i = -1e30f, l_i = 0.0f;
    float acc[16];
#pragma unroll
    for (int j = 0; j < 16; j++) acc[j] = 0.0f;

    const size_t mask_row_base = ((size_t)b * S_LEN + (size_t)(qt * 64 + r)) * S_LEN;

    for (int kt = 0; kt < 32; kt++) {
        // Load K and V tiles
        {
            const int t = kt * 64 + r;
            const float* src = g_mixed + (size_t)(t * BATCH + b) * QKV_N + h * 192;
#pragma unroll
            for (int i = 0; i < 16; i += 4) {
                float4 kv = *(const float4*)(src + 64 + c0 + i);
                Ks[r * 65 + c0 + i + 0] = kv.x;
                Ks[r * 65 + c0 + i + 1] = kv.y;
                Ks[r * 65 + c0 + i + 2] = kv.z;
                Ks[r * 65 + c0 + i + 3] = kv.w;
                float4 vv = *(const float4*)(src + 128 + c0 + i);
                Vs[r * 64 + c0 + i + 0] = vv.x;
                Vs[r * 64 + c0 + i + 1] = vv.y;
                Vs[r * 64 + c0 + i + 2] = vv.z;
                Vs[r * 64 + c0 + i + 3] = vv.w;
            }
        }
        __syncthreads();

        // Scores for (row r) x (cols c0..c0+15)
        float sc[16];
#pragma unroll
        for (int j = 0; j < 16; j++) sc[j] = 0.0f;
        for (int kk = 0; kk < 64; kk++) {
            const float qv = Qs[r * 64 + kk];
#pragma unroll
            for (int j = 0; j < 16; j++)
                sc[j] = fmaf(qv, Ks[(c0 + j) * 65 + kk], sc[j]);
        }

        // Scale + mask (dtype-adaptive mask load)
        const size_t moff = mask_row_base + (size_t)(kt * 64 + c0);
#pragma unroll
        for (int j = 0; j < 16; j++) {
            const int mv = mask_i32 ? mask_32[moff + j] : (int)mask_u8[moff + j];
            float v = sc[j] * 0.125f;
            sc[j] = mv ? MASK_VAL : v;
        }

        // Row max across 16 local + quad
        float rmax = sc[0];
#pragma unroll
        for (int j = 1; j < 16; j++) rmax = fmaxf(rmax, sc[j]);
        rmax = fmaxf(rmax, __shfl_xor_sync(0xFFFFFFFFu, rmax, 1));
        rmax = fmaxf(rmax, __shfl_xor_sync(0xFFFFFFFFu, rmax, 2));

        const float new_m = fmaxf(m_i, rmax);
        const float corr  = __expf(m_i - new_m);

        // Probabilities
        float lsum = 0.0f;
#pragma unroll
        for (int j = 0; j < 16; j++) {
            float p = __expf(sc[j] - new_m);
            lsum += p;
            Ps[r * 65 + c0 + j] = p;
        }
        lsum += __shfl_xor_sync(0xFFFFFFFFu, lsum, 1);
        lsum += __shfl_xor_sync(0xFFFFFFFFu, lsum, 2);

        l_i = l_i * corr + lsum;
        m_i = new_m;

        __syncthreads();

        // ctx update
#pragma unroll
        for (int j = 0; j < 16; j++) acc[j] *= corr;
        for (int kk = 0; kk < 64; kk++) {
            const float p = Ps[r * 65 + kk];
#pragma unroll
            for (int j = 0; j < 16; j++)
                acc[j] = fmaf(p, Vs[kk * 64 + c0 + j], acc[j]);
        }
        __syncthreads();
    }

    // Write normalized context
    const float inv = 1.0f / l_i;
    const int s = qt * 64 + r;
    float* dst = g_ctx + (size_t)(s * BATCH + b) * HID + h * HDIM + c0;
#pragma unroll
    for (int j = 0; j < 16; j++) dst[j] = acc[j] * inv;
}

// ---------------------------------------------------------------------------
// Launch
// ---------------------------------------------------------------------------
extern "C" void kernel_launch(void* const* d_in, const int* in_sizes, int n_in,
                              void* d_out, int out_size) {
    const float* hs      = (const float*)d_in[0];
    const void*  mask    = d_in[1];
    const float* W_qkv   = (const float*)d_in[2];
    const float* b_qkv   = (const float*)d_in[3];
    const float* W_dense = (const float*)d_in[4];
    const float* b_dense = (const float*)d_in[5];
    float* out = (float*)d_out;

    float* mixed;
    float* ctx;
    cudaGetSymbolAddress((void**)&mixed, g_mixed);
    cudaGetSymbolAddress((void**)&ctx, g_ctx);

    // 0) Detect mask dtype (bool may arrive as int32 or uint8)
    detect_mask_dtype<<<1, 1>>>((const int*)mask);

    // 1) QKV GEMM: [8192,1024] x [3072,1024]^T -> [8192,3072]
    {
        dim3 grid(QKV_N / 64, M_ROWS / 64);
        gemm_nt_bias<QKV_N, HID><<<grid, 256>>>(hs, W_qkv, b_qkv, mixed);
    }

    // 2) Flash attention -> ctx [8192,1024]
    {
        const int smem_bytes = (64 * 64 + 64 * 65 + 64 * 64 + 64 * 65) * sizeof(float);
        cudaFuncSetAttribute(attention_kernel,
                             cudaFuncAttributeMaxDynamicSharedMemorySize, smem_bytes);
        dim3 grid(S_LEN / 64, BATCH * NHEADS);
        attention_kernel<<<grid, 256, smem_bytes>>>(mask, ctx);
    }

    // 3) Dense GEMM: [8192,1024] x [1024,1024]^T -> out [8192,1024]
    {
        dim3 grid(HID / 64, M_ROWS / 64);
        gemm_nt_bias<HID, HID><<<grid, 256>>>(ctx, W_dense, b_dense, out);
    }
}